// round 5
// baseline (speedup 1.0000x reference)
#include <cuda_runtime.h>
#include <cuda_fp16.h>
#include <math.h>
#include <stdint.h>

#define TTOK 4096
#define HDIM 2048
#define NEXP 64
#define TOPK 8
#define IDIM 768
#define NPAIR (TTOK * TOPK)
#define CAP   TTOK

/* ---------------- scratch ---------------- */
__device__ float g_logits[TTOK * NEXP];
__device__ float g_topkw[NPAIR];
__device__ int   g_counts[NEXP];
__device__ int   g_offsets[NEXP];
__device__ int   g_bucket[NEXP * CAP];
__device__ uint4 g_act4[(size_t)NPAIR * IDIM / 8];   /* fp16 activations */

#define LD4(p) (*reinterpret_cast<const float4*>(p))

/* ---------------- helpers ---------------- */
__device__ __forceinline__ uint32_t smem_u32(const void* p) {
    uint32_t a;
    asm("{ .reg .u64 t; cvta.to.shared.u64 t, %1; cvt.u32.u64 %0, t; }" : "=r"(a) : "l"(p));
    return a;
}
__device__ __forceinline__ uint32_t pk2(float x, float y) {
    __half2 h = __floats2half2_rn(x, y);
    return *reinterpret_cast<uint32_t*>(&h);
}
__device__ __forceinline__ uint4 pack8(float4 a, float4 b) {
    return make_uint4(pk2(a.x, a.y), pk2(a.z, a.w), pk2(b.x, b.y), pk2(b.z, b.w));
}
__device__ __forceinline__ void ldsm4(uint32_t* r, uint32_t addr) {
    asm volatile("ldmatrix.sync.aligned.m8n8.x4.shared.b16 {%0,%1,%2,%3}, [%4];"
                 : "=r"(r[0]), "=r"(r[1]), "=r"(r[2]), "=r"(r[3]) : "r"(addr));
}
__device__ __forceinline__ void ldsm2t(uint32_t* r, uint32_t addr) {
    asm volatile("ldmatrix.sync.aligned.m8n8.x2.trans.shared.b16 {%0,%1}, [%2];"
                 : "=r"(r[0]), "=r"(r[1]) : "r"(addr));
}
__device__ __forceinline__ void mma16(float* d, const uint32_t* a, const uint32_t* b) {
    asm volatile(
        "mma.sync.aligned.m16n8k16.row.col.f32.f16.f16.f32 "
        "{%0,%1,%2,%3}, {%4,%5,%6,%7}, {%8,%9}, {%0,%1,%2,%3};"
        : "+f"(d[0]), "+f"(d[1]), "+f"(d[2]), "+f"(d[3])
        : "r"(a[0]), "r"(a[1]), "r"(a[2]), "r"(a[3]), "r"(b[0]), "r"(b[1]));
}

/* smem tiles (halves): A[256][24] (48B rows), B[16][136] (272B rows) */
#define A_LDA 24
#define B_LDB 136
#define A_HALVES (256 * A_LDA)            /* 6144 */
#define B_HALVES (16 * B_LDB)             /* 2176 */
#define G1_STAGE_H (A_HALVES + 2 * B_HALVES)      /* 10496 */
#define G1_SMEM (1024 + 2 * G1_STAGE_H * 2)
#define G2_STAGE_H (A_HALVES + B_HALVES)          /* 8320 */
#define G2_SMEM (1024 + 2 * G2_STAGE_H * 2)

/* ---------------- small kernels ---------------- */
__global__ void k_zero_counts() { if (threadIdx.x < NEXP) g_counts[threadIdx.x] = 0; }

__global__ void k_zero_out(float4* __restrict__ out) {
    size_t i = (size_t)blockIdx.x * blockDim.x + threadIdx.x;
    if (i < (size_t)TTOK * HDIM / 4) out[i] = make_float4(0.f, 0.f, 0.f, 0.f);
}

__global__ void __launch_bounds__(256) k_router(const float* __restrict__ x,
                                                const float* __restrict__ gw) {
    __shared__ float As[16][64];
    __shared__ float Bs[16][64];
    const int t = threadIdx.x;
    const int m0 = blockIdx.x * 64;
    const int tx = t & 15, ty = t >> 4;
    const int mload = t >> 2;
    const int kq = (t & 3) * 4;
    float acc[4][4] = {};
    for (int k0 = 0; k0 < HDIM; k0 += 16) {
        float4 av = LD4(x + (size_t)(m0 + mload) * HDIM + k0 + kq);
        float4 bv = LD4(gw + (size_t)mload * HDIM + k0 + kq);
        __syncthreads();
        As[kq + 0][mload] = av.x; As[kq + 1][mload] = av.y;
        As[kq + 2][mload] = av.z; As[kq + 3][mload] = av.w;
        Bs[kq + 0][mload] = bv.x; Bs[kq + 1][mload] = bv.y;
        Bs[kq + 2][mload] = bv.z; Bs[kq + 3][mload] = bv.w;
        __syncthreads();
#pragma unroll
        for (int k = 0; k < 16; k++) {
            float4 a = LD4(&As[k][ty * 4]);
            float4 b = LD4(&Bs[k][tx * 4]);
            float ax[4] = {a.x, a.y, a.z, a.w};
            float bx[4] = {b.x, b.y, b.z, b.w};
#pragma unroll
            for (int i = 0; i < 4; i++)
#pragma unroll
                for (int j = 0; j < 4; j++)
                    acc[i][j] = fmaf(ax[i], bx[j], acc[i][j]);
        }
    }
#pragma unroll
    for (int i = 0; i < 4; i++)
#pragma unroll
        for (int j = 0; j < 4; j++)
            g_logits[(size_t)(m0 + ty * 4 + i) * NEXP + tx * 4 + j] = acc[i][j];
}

__global__ void k_topk() {
    int t = blockIdx.x * blockDim.x + threadIdx.x;
    if (t >= TTOK) return;
    float l[NEXP];
    for (int e = 0; e < NEXP; e++) l[e] = g_logits[(size_t)t * NEXP + e];
    float vals[TOPK]; int ids[TOPK];
    for (int k = 0; k < TOPK; k++) {
        float best = -3.4e38f; int bi = 0;
        for (int e = 0; e < NEXP; e++)
            if (l[e] > best) { best = l[e]; bi = e; }
        vals[k] = best; ids[k] = bi; l[bi] = -3.4e38f;
    }
    float m = vals[0], s = 0.f, wv[TOPK];
    for (int k = 0; k < TOPK; k++) { wv[k] = expf(vals[k] - m); s += wv[k]; }
    float inv = 1.f / s;
    for (int k = 0; k < TOPK; k++) {
        g_topkw[t * TOPK + k] = wv[k] * inv;
        int e = ids[k];
        int pos = atomicAdd(&g_counts[e], 1);
        g_bucket[e * CAP + pos] = t * TOPK + k;
    }
}

__global__ void k_scan() {
    int s = 0;
    for (int e = 0; e < NEXP; e++) { g_offsets[e] = s; s += g_counts[e]; }
}

/* ================= stage 4: gate/up fp16 HMMA, CTA 256Mx64N, warp 64x32 ======= */
__global__ void __launch_bounds__(256)
k_gemm1(const float* __restrict__ x, const float* __restrict__ wgt, const float* __restrict__ wup) {
    extern __shared__ char smraw[];
    const int e = blockIdx.z;
    const int rows = g_counts[e];
    const int m0 = blockIdx.y * 256;
    if (m0 >= rows) return;
    const int n0 = blockIdx.x * 64;
    const int t = threadIdx.x, w = t >> 5, lane = t & 31;
    const int gid = lane >> 2, tig = lane & 3;
    const int wm = w >> 1, wn = w & 1;

    int* toks = (int*)smraw;
    __half* buf = (__half*)(smraw + 1024);
    {
        int r = m0 + t;
        toks[t] = (r < rows) ? (g_bucket[e * CAP + r] >> 3) : -1;
    }
    __syncthreads();

    const float* bg = wgt + (size_t)e * HDIM * IDIM;
    const float* bu = wup + (size_t)e * HDIM * IDIM;

    /* A fill: thread t -> row t, 16 k-floats */
    const int tokA = toks[t];
    const bool aval = (tokA >= 0);
    const float* aptr = x + (size_t)(aval ? tokA : 0) * HDIM;
    /* B fill: threads 0-127 gate, 128-255 up; q: k-row q>>3, n-oct (q&7)*8 */
    const int bq = t & 127, bk = bq >> 3, bn = (bq & 7) * 8;
    const float* bsrc = (t < 128) ? bg : bu;
    const int bhoff = A_HALVES + ((t < 128) ? 0 : B_HALVES);

    float4 pa0, pa1, pa2, pa3, pb0, pb1;
    if (aval) { pa0 = LD4(aptr); pa1 = LD4(aptr + 4); pa2 = LD4(aptr + 8); pa3 = LD4(aptr + 12); }
    else { pa0 = make_float4(0, 0, 0, 0); pa1 = pa0; pa2 = pa0; pa3 = pa0; }
    { const float* s = bsrc + (size_t)bk * IDIM + n0 + bn;
      pb0 = LD4(s); pb1 = LD4(s + 4); }

    float cg[4][4][4] = {}, cu[4][4][4] = {};

    const int aRow = wm * 64 + (lane & 15);
    const int aK   = (lane >> 4) * 8;
    const int bK   = lane & 15;

    const int KT = HDIM / 16;
    for (int kt = 0; kt < KT; kt++) {
        __half* st = buf + (kt & 1) * G1_STAGE_H;
        __syncthreads();
        *reinterpret_cast<uint4*>(st + t * A_LDA)     = pack8(pa0, pa1);
        *reinterpret_cast<uint4*>(st + t * A_LDA + 8) = pack8(pa2, pa3);
        *reinterpret_cast<uint4*>(st + bhoff + bk * B_LDB + bn) = pack8(pb0, pb1);
        __syncthreads();
        if (kt + 1 < KT) {
            const int kb = (kt + 1) * 16;
            if (aval) { pa0 = LD4(aptr + kb); pa1 = LD4(aptr + kb + 4);
                        pa2 = LD4(aptr + kb + 8); pa3 = LD4(aptr + kb + 12); }
            const float* s = bsrc + (size_t)(kb + bk) * IDIM + n0 + bn;
            pb0 = LD4(s); pb1 = LD4(s + 4);
        }
        const uint32_t aAddr  = smem_u32(st + aRow * A_LDA + aK);
        const uint32_t bgAddr = smem_u32(st + A_HALVES + bK * B_LDB + wn * 32);
        const uint32_t buAddr = bgAddr + B_HALVES * 2;
        uint32_t af[4][4];
#pragma unroll
        for (int mt = 0; mt < 4; mt++) ldsm4(af[mt], aAddr + mt * 16 * A_LDA * 2);
#pragma unroll
        for (int nt = 0; nt < 4; nt++) {
            uint32_t b[2];
            ldsm2t(b, bgAddr + nt * 16);
#pragma unroll
            for (int mt = 0; mt < 4; mt++) mma16(cg[mt][nt], af[mt], b);
            ldsm2t(b, buAddr + nt * 16);
#pragma unroll
            for (int mt = 0; mt < 4; mt++) mma16(cu[mt][nt], af[mt], b);
        }
    }
    /* fused SiLU epilogue -> g_act (fp16) */
    __half* gact = (__half*)g_act4;
    const int off = g_offsets[e];
#pragma unroll
    for (int mt = 0; mt < 4; mt++) {
#pragma unroll
        for (int h = 0; h < 2; h++) {
            const int row = m0 + wm * 64 + mt * 16 + gid + h * 8;
            if (row < rows) {
                __half* dst = gact + (size_t)(off + row) * IDIM + n0 + wn * 32;
#pragma unroll
                for (int nt = 0; nt < 4; nt++) {
                    float g0 = cg[mt][nt][h * 2 + 0], g1 = cg[mt][nt][h * 2 + 1];
                    float u0 = cu[mt][nt][h * 2 + 0], u1 = cu[mt][nt][h * 2 + 1];
                    float o0 = g0 / (1.f + expf(-g0)) * u0;
                    float o1 = g1 / (1.f + expf(-g1)) * u1;
                    *reinterpret_cast<uint32_t*>(dst + nt * 8 + 2 * tig) = pk2(o0, o1);
                }
            }
        }
    }
}

/* ============ stage 5: down-proj fp16 HMMA, CTA 256Mx128N, warp 64x64 ========= */
__global__ void __launch_bounds__(256)
k_gemm2(const float* __restrict__ wdn, float* __restrict__ out) {
    extern __shared__ char smraw[];
    const int e = blockIdx.z;
    const int rows = g_counts[e];
    const int m0 = blockIdx.y * 256;
    if (m0 >= rows) return;
    const int n0 = blockIdx.x * 128;
    const int t = threadIdx.x, w = t >> 5, lane = t & 31;
    const int gid = lane >> 2, tig = lane & 3;
    const int wm = w >> 1, wn = w & 1;
    const int off = g_offsets[e];

    int* prs = (int*)smraw;
    __half* buf = (__half*)(smraw + 1024);
    {
        int r = m0 + t;
        prs[t] = (r < rows) ? g_bucket[e * CAP + r] : -1;
    }
    __syncthreads();

    const float* bsrc = wdn + (size_t)e * IDIM * HDIM;
    const __half* gact = (const __half*)g_act4;

    const bool aval = (m0 + t < rows);
    const __half* aptr = gact + (size_t)(off + m0 + (aval ? t : 0)) * IDIM;
    const int bk = t >> 4, bn = (t & 15) * 8;

    uint4 pa0, pa1; float4 pb0, pb1;
    if (aval) { pa0 = *reinterpret_cast<const uint4*>(aptr);
                pa1 = *reinterpret_cast<const uint4*>(aptr + 8); }
    else { pa0 = make_uint4(0, 0, 0, 0); pa1 = pa0; }
    { const float* s = bsrc + (size_t)bk * HDIM + n0 + bn;
      pb0 = LD4(s); pb1 = LD4(s + 4); }

    float cd[4][8][4] = {};

    const int aRow = wm * 64 + (lane & 15);
    const int aK   = (lane >> 4) * 8;
    const int bK   = lane & 15;

    const int KT = IDIM / 16;
    for (int kt = 0; kt < KT; kt++) {
        __half* st = buf + (kt & 1) * G2_STAGE_H;
        __syncthreads();
        *reinterpret_cast<uint4*>(st + t * A_LDA)     = pa0;
        *reinterpret_cast<uint4*>(st + t * A_LDA + 8) = pa1;
        *reinterpret_cast<uint4*>(st + A_HALVES + bk * B_LDB + bn) = pack8(pb0, pb1);
        __syncthreads();
        if (kt + 1 < KT) {
            const int kb = (kt + 1) * 16;
            if (aval) { pa0 = *reinterpret_cast<const uint4*>(aptr + kb);
                        pa1 = *reinterpret_cast<const uint4*>(aptr + kb + 8); }
            const float* s = bsrc + (size_t)(kb + bk) * HDIM + n0 + bn;
            pb0 = LD4(s); pb1 = LD4(s + 4);
        }
        const uint32_t aAddr = smem_u32(st + aRow * A_LDA + aK);
        const uint32_t bAddr = smem_u32(st + A_HALVES + bK * B_LDB + wn * 64);
        uint32_t af[4][4];
#pragma unroll
        for (int mt = 0; mt < 4; mt++) ldsm4(af[mt], aAddr + mt * 16 * A_LDA * 2);
#pragma unroll
        for (int nt = 0; nt < 8; nt++) {
            uint32_t b[2];
            ldsm2t(b, bAddr + nt * 16);
#pragma unroll
            for (int mt = 0; mt < 4; mt++) mma16(cd[mt][nt], af[mt], b);
        }
    }
    /* fused combine: scale by routing weight, atomic accumulate into out */
#pragma unroll
    for (int mt = 0; mt < 4; mt++) {
#pragma unroll
        for (int h = 0; h < 2; h++) {
            const int lr = wm * 64 + mt * 16 + gid + h * 8;
            const int p = prs[lr];
            if (p >= 0) {
                const float wv = g_topkw[p];
                const int tok = p >> 3;
                float* dst = out + (size_t)tok * HDIM + n0 + wn * 64;
#pragma unroll
                for (int nt = 0; nt < 8; nt++) {
                    atomicAdd(dst + nt * 8 + 2 * tig,     wv * cd[mt][nt][h * 2 + 0]);
                    atomicAdd(dst + nt * 8 + 2 * tig + 1, wv * cd[mt][nt][h * 2 + 1]);
                }
            }
        }
    }
}

/* ---------------- launch ---------------- */
extern "C" void kernel_launch(void* const* d_in, const int* /*in_sizes*/, int /*n_in*/,
                              void* d_out, int /*out_size*/) {
    const float* x   = (const float*)d_in[0];
    const float* gw  = (const float*)d_in[1];
    const float* wgt = (const float*)d_in[2];
    const float* wup = (const float*)d_in[3];
    const float* wdn = (const float*)d_in[4];
    float* out = (float*)d_out;

    cudaFuncSetAttribute(k_gemm1, cudaFuncAttributeMaxDynamicSharedMemorySize, G1_SMEM);
    cudaFuncSetAttribute(k_gemm2, cudaFuncAttributeMaxDynamicSharedMemorySize, G2_SMEM);

    k_zero_out<<<TTOK * HDIM / 4 / 256, 256>>>((float4*)out);
    k_zero_counts<<<1, 64>>>();
    k_router<<<TTOK / 64, 256>>>(x, gw);
    k_topk<<<TTOK / 256, 256>>>();
    k_scan<<<1, 1>>>();
    k_gemm1<<<dim3(IDIM / 64, CAP / 256, NEXP), 256, G1_SMEM>>>(x, wgt, wup);
    k_gemm2<<<dim3(HDIM / 128, CAP / 256, NEXP), 256, G2_SMEM>>>(wdn, out);
}

// round 6
// speedup vs baseline: 1.2999x; 1.2999x over previous
#include <cuda_runtime.h>
#include <cuda_fp16.h>
#include <math.h>
#include <stdint.h>

#define TTOK 4096
#define HDIM 2048
#define NEXP 64
#define TOPK 8
#define IDIM 768
#define NPAIR (TTOK * TOPK)
#define CAP   TTOK

/* ---------------- scratch ---------------- */
__device__ float g_logits[TTOK * NEXP];
__device__ float g_topkw[NPAIR];
__device__ int   g_counts[NEXP];
__device__ int   g_offsets[NEXP];
__device__ int   g_bucket[NEXP * CAP];
__device__ uint4 g_act4[(size_t)NPAIR * IDIM / 8];   /* fp16 activations */

#define LD4(p) (*reinterpret_cast<const float4*>(p))

/* ---------------- helpers ---------------- */
__device__ __forceinline__ uint32_t smem_u32(const void* p) {
    uint32_t a;
    asm("{ .reg .u64 t; cvta.to.shared.u64 t, %1; cvt.u32.u64 %0, t; }" : "=r"(a) : "l"(p));
    return a;
}
__device__ __forceinline__ uint32_t pk2(float x, float y) {
    __half2 h = __floats2half2_rn(x, y);
    return *reinterpret_cast<uint32_t*>(&h);
}
__device__ __forceinline__ uint4 pack8(float4 a, float4 b) {
    return make_uint4(pk2(a.x, a.y), pk2(a.z, a.w), pk2(b.x, b.y), pk2(b.z, b.w));
}
__device__ __forceinline__ void ldsm4(uint32_t* r, uint32_t addr) {
    asm volatile("ldmatrix.sync.aligned.m8n8.x4.shared.b16 {%0,%1,%2,%3}, [%4];"
                 : "=r"(r[0]), "=r"(r[1]), "=r"(r[2]), "=r"(r[3]) : "r"(addr));
}
__device__ __forceinline__ void ldsm2t(uint32_t* r, uint32_t addr) {
    asm volatile("ldmatrix.sync.aligned.m8n8.x2.trans.shared.b16 {%0,%1}, [%2];"
                 : "=r"(r[0]), "=r"(r[1]) : "r"(addr));
}
__device__ __forceinline__ void mma16(float* d, const uint32_t* a, const uint32_t* b) {
    asm volatile(
        "mma.sync.aligned.m16n8k16.row.col.f32.f16.f16.f32 "
        "{%0,%1,%2,%3}, {%4,%5,%6,%7}, {%8,%9}, {%0,%1,%2,%3};"
        : "+f"(d[0]), "+f"(d[1]), "+f"(d[2]), "+f"(d[3])
        : "r"(a[0]), "r"(a[1]), "r"(a[2]), "r"(a[3]), "r"(b[0]), "r"(b[1]));
}

/* smem tiles (halves): A[128][24] (48B rows), B[16][136] (272B rows) */
#define A_LDA 24
#define B_LDB 136
#define A_HALVES (128 * A_LDA)            /* 3072 */
#define B_HALVES (16 * B_LDB)             /* 2176 */
#define G1_STAGE_H (A_HALVES + 2 * B_HALVES)      /* 7424 */
#define G1_SMEM (512 + 3 * G1_STAGE_H * 2)
#define G2_STAGE_H (A_HALVES + B_HALVES)          /* 5248 */
#define G2_SMEM (512 + 3 * G2_STAGE_H * 2)

/* ---------------- small kernels ---------------- */
__global__ void k_zero_counts() { if (threadIdx.x < NEXP) g_counts[threadIdx.x] = 0; }

__global__ void k_zero_out(float4* __restrict__ out) {
    size_t i = (size_t)blockIdx.x * blockDim.x + threadIdx.x;
    if (i < (size_t)TTOK * HDIM / 4) out[i] = make_float4(0.f, 0.f, 0.f, 0.f);
}

__global__ void __launch_bounds__(256) k_router(const float* __restrict__ x,
                                                const float* __restrict__ gw) {
    __shared__ float As[16][64];
    __shared__ float Bs[16][64];
    const int t = threadIdx.x;
    const int m0 = blockIdx.x * 64;
    const int tx = t & 15, ty = t >> 4;
    const int mload = t >> 2;
    const int kq = (t & 3) * 4;
    float acc[4][4] = {};
    for (int k0 = 0; k0 < HDIM; k0 += 16) {
        float4 av = LD4(x + (size_t)(m0 + mload) * HDIM + k0 + kq);
        float4 bv = LD4(gw + (size_t)mload * HDIM + k0 + kq);
        __syncthreads();
        As[kq + 0][mload] = av.x; As[kq + 1][mload] = av.y;
        As[kq + 2][mload] = av.z; As[kq + 3][mload] = av.w;
        Bs[kq + 0][mload] = bv.x; Bs[kq + 1][mload] = bv.y;
        Bs[kq + 2][mload] = bv.z; Bs[kq + 3][mload] = bv.w;
        __syncthreads();
#pragma unroll
        for (int k = 0; k < 16; k++) {
            float4 a = LD4(&As[k][ty * 4]);
            float4 b = LD4(&Bs[k][tx * 4]);
            float ax[4] = {a.x, a.y, a.z, a.w};
            float bx[4] = {b.x, b.y, b.z, b.w};
#pragma unroll
            for (int i = 0; i < 4; i++)
#pragma unroll
                for (int j = 0; j < 4; j++)
                    acc[i][j] = fmaf(ax[i], bx[j], acc[i][j]);
        }
    }
#pragma unroll
    for (int i = 0; i < 4; i++)
#pragma unroll
        for (int j = 0; j < 4; j++)
            g_logits[(size_t)(m0 + ty * 4 + i) * NEXP + tx * 4 + j] = acc[i][j];
}

__global__ void k_topk() {
    int t = blockIdx.x * blockDim.x + threadIdx.x;
    if (t >= TTOK) return;
    float l[NEXP];
    for (int e = 0; e < NEXP; e++) l[e] = g_logits[(size_t)t * NEXP + e];
    float vals[TOPK]; int ids[TOPK];
    for (int k = 0; k < TOPK; k++) {
        float best = -3.4e38f; int bi = 0;
        for (int e = 0; e < NEXP; e++)
            if (l[e] > best) { best = l[e]; bi = e; }
        vals[k] = best; ids[k] = bi; l[bi] = -3.4e38f;
    }
    float m = vals[0], s = 0.f, wv[TOPK];
    for (int k = 0; k < TOPK; k++) { wv[k] = expf(vals[k] - m); s += wv[k]; }
    float inv = 1.f / s;
    for (int k = 0; k < TOPK; k++) {
        g_topkw[t * TOPK + k] = wv[k] * inv;
        int e = ids[k];
        int pos = atomicAdd(&g_counts[e], 1);
        g_bucket[e * CAP + pos] = t * TOPK + k;
    }
}

__global__ void k_scan() {
    int s = 0;
    for (int e = 0; e < NEXP; e++) { g_offsets[e] = s; s += g_counts[e]; }
}

/* ======= stage 4: gate/up fp16 HMMA, CTA 128x128, 3-stage pipe, 1 sync/iter ===== */
__global__ void __launch_bounds__(256)
k_gemm1(const float* __restrict__ x, const float* __restrict__ wgt, const float* __restrict__ wup) {
    extern __shared__ char smraw[];
    const int e = blockIdx.z;
    const int rows = g_counts[e];
    const int m0 = blockIdx.y * 128;
    if (m0 >= rows) return;
    const int n0 = blockIdx.x * 128;
    const int t = threadIdx.x, w = t >> 5, lane = t & 31;
    const int gid = lane >> 2, tig = lane & 3;
    const int wm = w >> 2, wn = w & 3;

    int* toks = (int*)smraw;
    __half* buf = (__half*)(smraw + 512);
    if (t < 128) {
        int r = m0 + t;
        toks[t] = (r < rows) ? (g_bucket[e * CAP + r] >> 3) : -1;
    }
    __syncthreads();

    const float* bg = wgt + (size_t)e * HDIM * IDIM;
    const float* bu = wup + (size_t)e * HDIM * IDIM;

    const int am = t >> 1, akh = (t & 1) * 8;
    const int tokA = toks[am];
    const bool aval = (tokA >= 0);
    const float* aptr = x + (size_t)(aval ? tokA : 0) * HDIM;
    const int bq = t & 127, bk = bq >> 3, bn = (bq & 7) * 16;
    const float* bsrc = (t < 128) ? bg : bu;
    const int bhoff = A_HALVES + ((t < 128) ? 0 : B_HALVES);

    float4 pa0 = make_float4(0, 0, 0, 0), pa1 = pa0, pb0, pb1, pb2, pb3;

    /* load kt=0 */
    if (aval) { pa0 = LD4(aptr + akh); pa1 = LD4(aptr + akh + 4); }
    { const float* s = bsrc + (size_t)bk * IDIM + n0 + bn;
      pb0 = LD4(s); pb1 = LD4(s + 4); pb2 = LD4(s + 8); pb3 = LD4(s + 12); }
    /* STS stage 0 */
    {
        __half* st = buf;
        *reinterpret_cast<uint4*>(st + am * A_LDA + akh) = pack8(pa0, pa1);
        __half* p = st + bhoff + bk * B_LDB + bn;
        *reinterpret_cast<uint4*>(p)     = pack8(pb0, pb1);
        *reinterpret_cast<uint4*>(p + 8) = pack8(pb2, pb3);
    }
    /* load kt=1 */
    if (aval) { pa0 = LD4(aptr + 16 + akh); pa1 = LD4(aptr + 16 + akh + 4); }
    { const float* s = bsrc + (size_t)(16 + bk) * IDIM + n0 + bn;
      pb0 = LD4(s); pb1 = LD4(s + 4); pb2 = LD4(s + 8); pb3 = LD4(s + 12); }
    __syncthreads();

    float cg[4][4][4] = {}, cu[4][4][4] = {};

    const int aRow = wm * 64 + (lane & 15);
    const int aK   = (lane >> 4) * 8;
    const int bK   = lane & 15;

    const int KT = HDIM / 16;
    int ri = 0;
    for (int kt = 0; kt < KT; kt++) {
        __half* stc = buf + ri * G1_STAGE_H;
        int wi = ri + 1; if (wi == 3) wi = 0;
        if (kt + 1 < KT) {            /* STS regs (hold kt+1) into stage wi */
            __half* st = buf + wi * G1_STAGE_H;
            *reinterpret_cast<uint4*>(st + am * A_LDA + akh) = pack8(pa0, pa1);
            __half* p = st + bhoff + bk * B_LDB + bn;
            *reinterpret_cast<uint4*>(p)     = pack8(pb0, pb1);
            *reinterpret_cast<uint4*>(p + 8) = pack8(pb2, pb3);
        }
        if (kt + 2 < KT) {            /* load regs kt+2 */
            const int kb = (kt + 2) * 16;
            if (aval) { pa0 = LD4(aptr + kb + akh); pa1 = LD4(aptr + kb + akh + 4); }
            const float* s = bsrc + (size_t)(kb + bk) * IDIM + n0 + bn;
            pb0 = LD4(s); pb1 = LD4(s + 4); pb2 = LD4(s + 8); pb3 = LD4(s + 12);
        }
        if (kt + 1 < KT) __syncthreads();
        /* compute on stage ri */
        const uint32_t aAddr  = smem_u32(stc + aRow * A_LDA + aK);
        const uint32_t bgAddr = smem_u32(stc + A_HALVES + bK * B_LDB + wn * 32);
        const uint32_t buAddr = bgAddr + B_HALVES * 2;
        uint32_t af[4][4];
#pragma unroll
        for (int mt = 0; mt < 4; mt++) ldsm4(af[mt], aAddr + mt * 16 * A_LDA * 2);
#pragma unroll
        for (int nt = 0; nt < 4; nt++) {
            uint32_t b[2];
            ldsm2t(b, bgAddr + nt * 16);
#pragma unroll
            for (int mt = 0; mt < 4; mt++) mma16(cg[mt][nt], af[mt], b);
            ldsm2t(b, buAddr + nt * 16);
#pragma unroll
            for (int mt = 0; mt < 4; mt++) mma16(cu[mt][nt], af[mt], b);
        }
        ri = wi;
    }
    /* fused SiLU epilogue -> g_act (fp16) */
    __half* gact = (__half*)g_act4;
    const int off = g_offsets[e];
#pragma unroll
    for (int mt = 0; mt < 4; mt++) {
#pragma unroll
        for (int h = 0; h < 2; h++) {
            const int row = m0 + wm * 64 + mt * 16 + gid + h * 8;
            if (row < rows) {
                __half* dst = gact + (size_t)(off + row) * IDIM + n0 + wn * 32;
#pragma unroll
                for (int nt = 0; nt < 4; nt++) {
                    float g0 = cg[mt][nt][h * 2 + 0], g1 = cg[mt][nt][h * 2 + 1];
                    float u0 = cu[mt][nt][h * 2 + 0], u1 = cu[mt][nt][h * 2 + 1];
                    float o0 = g0 / (1.f + expf(-g0)) * u0;
                    float o1 = g1 / (1.f + expf(-g1)) * u1;
                    *reinterpret_cast<uint32_t*>(dst + nt * 8 + 2 * tig) = pk2(o0, o1);
                }
            }
        }
    }
}

/* ===== stage 5: down-proj fp16 HMMA + fused combine, 3-stage pipe, 1 sync/iter == */
__global__ void __launch_bounds__(256)
k_gemm2(const float* __restrict__ wdn, float* __restrict__ out) {
    extern __shared__ char smraw[];
    const int e = blockIdx.z;
    const int rows = g_counts[e];
    const int m0 = blockIdx.y * 128;
    if (m0 >= rows) return;
    const int n0 = blockIdx.x * 128;
    const int t = threadIdx.x, w = t >> 5, lane = t & 31;
    const int gid = lane >> 2, tig = lane & 3;
    const int wm = w >> 2, wn = w & 3;
    const int off = g_offsets[e];

    int* prs = (int*)smraw;
    __half* buf = (__half*)(smraw + 512);
    if (t < 128) {
        int r = m0 + t;
        prs[t] = (r < rows) ? g_bucket[e * CAP + r] : -1;
    }
    __syncthreads();

    const float* bsrc = wdn + (size_t)e * IDIM * HDIM;
    const __half* gact = (const __half*)g_act4;

    const int am = t >> 1, akh = (t & 1) * 8;
    const bool aval = (m0 + am < rows);
    const __half* aptr = gact + (size_t)(off + m0 + (aval ? am : 0)) * IDIM;
    const int bk = t >> 4, bn = (t & 15) * 8;

    uint4 pa = make_uint4(0, 0, 0, 0); float4 pb0, pb1;

    if (aval) pa = *reinterpret_cast<const uint4*>(aptr + akh);
    { const float* s = bsrc + (size_t)bk * HDIM + n0 + bn;
      pb0 = LD4(s); pb1 = LD4(s + 4); }
    {
        __half* st = buf;
        *reinterpret_cast<uint4*>(st + am * A_LDA + akh) = pa;
        *reinterpret_cast<uint4*>(st + A_HALVES + bk * B_LDB + bn) = pack8(pb0, pb1);
    }
    if (aval) pa = *reinterpret_cast<const uint4*>(aptr + 16 + akh);
    { const float* s = bsrc + (size_t)(16 + bk) * HDIM + n0 + bn;
      pb0 = LD4(s); pb1 = LD4(s + 4); }
    __syncthreads();

    float cd[4][4][4] = {};

    const int aRow = wm * 64 + (lane & 15);
    const int aK   = (lane >> 4) * 8;
    const int bK   = lane & 15;

    const int KT = IDIM / 16;
    int ri = 0;
    for (int kt = 0; kt < KT; kt++) {
        __half* stc = buf + ri * G2_STAGE_H;
        int wi = ri + 1; if (wi == 3) wi = 0;
        if (kt + 1 < KT) {
            __half* st = buf + wi * G2_STAGE_H;
            *reinterpret_cast<uint4*>(st + am * A_LDA + akh) = pa;
            *reinterpret_cast<uint4*>(st + A_HALVES + bk * B_LDB + bn) = pack8(pb0, pb1);
        }
        if (kt + 2 < KT) {
            const int kb = (kt + 2) * 16;
            if (aval) pa = *reinterpret_cast<const uint4*>(aptr + kb + akh);
            const float* s = bsrc + (size_t)(kb + bk) * HDIM + n0 + bn;
            pb0 = LD4(s); pb1 = LD4(s + 4);
        }
        if (kt + 1 < KT) __syncthreads();
        const uint32_t aAddr = smem_u32(stc + aRow * A_LDA + aK);
        const uint32_t bAddr = smem_u32(stc + A_HALVES + bK * B_LDB + wn * 32);
        uint32_t af[4][4];
#pragma unroll
        for (int mt = 0; mt < 4; mt++) ldsm4(af[mt], aAddr + mt * 16 * A_LDA * 2);
#pragma unroll
        for (int nt = 0; nt < 4; nt++) {
            uint32_t b[2];
            ldsm2t(b, bAddr + nt * 16);
#pragma unroll
            for (int mt = 0; mt < 4; mt++) mma16(cd[mt][nt], af[mt], b);
        }
        ri = wi;
    }
    /* fused combine: scale by routing weight, atomic accumulate into out */
#pragma unroll
    for (int mt = 0; mt < 4; mt++) {
#pragma unroll
        for (int h = 0; h < 2; h++) {
            const int lr = wm * 64 + mt * 16 + gid + h * 8;
            const int p = prs[lr];
            if (p >= 0) {
                const float wv = g_topkw[p];
                const int tok = p >> 3;
                float* dst = out + (size_t)tok * HDIM + n0 + wn * 32;
#pragma unroll
                for (int nt = 0; nt < 4; nt++) {
                    atomicAdd(dst + nt * 8 + 2 * tig,     wv * cd[mt][nt][h * 2 + 0]);
                    atomicAdd(dst + nt * 8 + 2 * tig + 1, wv * cd[mt][nt][h * 2 + 1]);
                }
            }
        }
    }
}

/* ---------------- launch ---------------- */
extern "C" void kernel_launch(void* const* d_in, const int* /*in_sizes*/, int /*n_in*/,
                              void* d_out, int /*out_size*/) {
    const float* x   = (const float*)d_in[0];
    const float* gw  = (const float*)d_in[1];
    const float* wgt = (const float*)d_in[2];
    const float* wup = (const float*)d_in[3];
    const float* wdn = (const float*)d_in[4];
    float* out = (float*)d_out;

    cudaFuncSetAttribute(k_gemm1, cudaFuncAttributeMaxDynamicSharedMemorySize, G1_SMEM);
    cudaFuncSetAttribute(k_gemm2, cudaFuncAttributeMaxDynamicSharedMemorySize, G2_SMEM);

    k_zero_out<<<TTOK * HDIM / 4 / 256, 256>>>((float4*)out);
    k_zero_counts<<<1, 64>>>();
    k_router<<<TTOK / 64, 256>>>(x, gw);
    k_topk<<<TTOK / 256, 256>>>();
    k_scan<<<1, 1>>>();
    k_gemm1<<<dim3(IDIM / 128, CAP / 128, NEXP), 256, G1_SMEM>>>(x, wgt, wup);
    k_gemm2<<<dim3(HDIM / 128, CAP / 128, NEXP), 256, G2_SMEM>>>(wdn, out);
}

// round 9
// speedup vs baseline: 1.4313x; 1.1011x over previous
#include <cuda_runtime.h>
#include <cuda_fp16.h>
#include <math.h>
#include <stdint.h>

#define TTOK 4096
#define HDIM 2048
#define NEXP 64
#define TOPK 8
#define IDIM 768
#define NPAIR (TTOK * TOPK)
#define CAP   TTOK

/* ---------------- scratch ---------------- */
__device__ float g_logits[TTOK * NEXP];
__device__ float g_topkw[NPAIR];
__device__ int   g_counts[NEXP];
__device__ int   g_offsets[NEXP];
__device__ int   g_bucket[NEXP * CAP];
__device__ uint4 g_act4[(size_t)NPAIR * IDIM / 8];          /* fp16 activations   */
__device__ uint4 g_xh[(size_t)TTOK * HDIM / 8];             /* fp16 tokens        */
__device__ uint4 g_wgh[(size_t)NEXP * HDIM * IDIM / 8];     /* fp16 w_gate        */
__device__ uint4 g_wuh[(size_t)NEXP * HDIM * IDIM / 8];     /* fp16 w_up          */
__device__ uint4 g_wdh[(size_t)NEXP * IDIM * HDIM / 8];     /* fp16 w_down        */

#define LD4(p) (*reinterpret_cast<const float4*>(p))

/* ---------------- helpers ---------------- */
__device__ __forceinline__ uint32_t smem_u32(const void* p) {
    uint32_t a;
    asm("{ .reg .u64 t; cvta.to.shared.u64 t, %1; cvt.u32.u64 %0, t; }" : "=r"(a) : "l"(p));
    return a;
}
__device__ __forceinline__ uint32_t pk2(float x, float y) {
    __half2 h = __floats2half2_rn(x, y);
    return *reinterpret_cast<uint32_t*>(&h);
}
__device__ __forceinline__ void ldsm4(uint32_t* r, uint32_t addr) {
    asm volatile("ldmatrix.sync.aligned.m8n8.x4.shared.b16 {%0,%1,%2,%3}, [%4];"
                 : "=r"(r[0]), "=r"(r[1]), "=r"(r[2]), "=r"(r[3]) : "r"(addr));
}
__device__ __forceinline__ void ldsm2t(uint32_t* r, uint32_t addr) {
    asm volatile("ldmatrix.sync.aligned.m8n8.x2.trans.shared.b16 {%0,%1}, [%2];"
                 : "=r"(r[0]), "=r"(r[1]) : "r"(addr));
}
__device__ __forceinline__ void mma16(float* d, const uint32_t* a, const uint32_t* b) {
    asm volatile(
        "mma.sync.aligned.m16n8k16.row.col.f32.f16.f16.f32 "
        "{%0,%1,%2,%3}, {%4,%5,%6,%7}, {%8,%9}, {%0,%1,%2,%3};"
        : "+f"(d[0]), "+f"(d[1]), "+f"(d[2]), "+f"(d[3])
        : "r"(a[0]), "r"(a[1]), "r"(a[2]), "r"(a[3]), "r"(b[0]), "r"(b[1]));
}
__device__ __forceinline__ void cpa16(uint32_t sdst, const void* gsrc, uint32_t sz) {
    asm volatile("cp.async.cg.shared.global [%0], [%1], 16, %2;"
                 :: "r"(sdst), "l"(gsrc), "r"(sz) : "memory");
}
__device__ __forceinline__ void cpa_commit() {
    asm volatile("cp.async.commit_group;" ::: "memory");
}
__device__ __forceinline__ void cpa_wait1() {
    asm volatile("cp.async.wait_group 1;" ::: "memory");
}

/* smem tiles (halves): A[128][24] (48B rows), B[16][136] (272B rows) */
#define A_LDA 24
#define B_LDB 136
#define A_HALVES (128 * A_LDA)
#define B_HALVES (16 * B_LDB)
#define G1_STAGE_H (A_HALVES + 2 * B_HALVES)
#define G1_SMEM (512 + 3 * G1_STAGE_H * 2)
#define G2_STAGE_H (A_HALVES + B_HALVES)
#define G2_SMEM (512 + 3 * G2_STAGE_H * 2)

/* ---------------- small kernels ---------------- */
__global__ void k_zero_counts() { if (threadIdx.x < NEXP) g_counts[threadIdx.x] = 0; }

__global__ void k_zero_out(float4* __restrict__ out) {
    size_t i = (size_t)blockIdx.x * blockDim.x + threadIdx.x;
    if (i < (size_t)TTOK * HDIM / 4) out[i] = make_float4(0.f, 0.f, 0.f, 0.f);
}

/* fp32 -> fp16 bulk convert. dst selected DEVICE-SIDE (passing a __device__
   symbol from host code passes the host shadow address — silent corruption). */
__global__ void __launch_bounds__(256) k_cvt(const float4* __restrict__ src,
                                             int which, size_t n8) {
    size_t i = (size_t)blockIdx.x * blockDim.x + threadIdx.x;
    if (i >= n8) return;
    uint4* dst = (which == 0) ? g_wgh : (which == 1) ? g_wuh : (which == 2) ? g_wdh : g_xh;
    float4 a = src[2 * i], b = src[2 * i + 1];
    dst[i] = make_uint4(pk2(a.x, a.y), pk2(a.z, a.w), pk2(b.x, b.y), pk2(b.z, b.w));
}

__global__ void __launch_bounds__(256) k_router(const float* __restrict__ x,
                                                const float* __restrict__ gw) {
    __shared__ float As[16][64];
    __shared__ float Bs[16][64];
    const int t = threadIdx.x;
    const int m0 = blockIdx.x * 64;
    const int tx = t & 15, ty = t >> 4;
    const int mload = t >> 2;
    const int kq = (t & 3) * 4;
    float acc[4][4] = {};
    for (int k0 = 0; k0 < HDIM; k0 += 16) {
        float4 av = LD4(x + (size_t)(m0 + mload) * HDIM + k0 + kq);
        float4 bv = LD4(gw + (size_t)mload * HDIM + k0 + kq);
        __syncthreads();
        As[kq + 0][mload] = av.x; As[kq + 1][mload] = av.y;
        As[kq + 2][mload] = av.z; As[kq + 3][mload] = av.w;
        Bs[kq + 0][mload] = bv.x; Bs[kq + 1][mload] = bv.y;
        Bs[kq + 2][mload] = bv.z; Bs[kq + 3][mload] = bv.w;
        __syncthreads();
#pragma unroll
        for (int k = 0; k < 16; k++) {
            float4 a = LD4(&As[k][ty * 4]);
            float4 b = LD4(&Bs[k][tx * 4]);
            float ax[4] = {a.x, a.y, a.z, a.w};
            float bx[4] = {b.x, b.y, b.z, b.w};
#pragma unroll
            for (int i = 0; i < 4; i++)
#pragma unroll
                for (int j = 0; j < 4; j++)
                    acc[i][j] = fmaf(ax[i], bx[j], acc[i][j]);
        }
    }
#pragma unroll
    for (int i = 0; i < 4; i++)
#pragma unroll
        for (int j = 0; j < 4; j++)
            g_logits[(size_t)(m0 + ty * 4 + i) * NEXP + tx * 4 + j] = acc[i][j];
}

__global__ void k_topk() {
    int t = blockIdx.x * blockDim.x + threadIdx.x;
    if (t >= TTOK) return;
    float l[NEXP];
    for (int e = 0; e < NEXP; e++) l[e] = g_logits[(size_t)t * NEXP + e];
    float vals[TOPK]; int ids[TOPK];
    for (int k = 0; k < TOPK; k++) {
        float best = -3.4e38f; int bi = 0;
        for (int e = 0; e < NEXP; e++)
            if (l[e] > best) { best = l[e]; bi = e; }
        vals[k] = best; ids[k] = bi; l[bi] = -3.4e38f;
    }
    float m = vals[0], s = 0.f, wv[TOPK];
    for (int k = 0; k < TOPK; k++) { wv[k] = expf(vals[k] - m); s += wv[k]; }
    float inv = 1.f / s;
    for (int k = 0; k < TOPK; k++) {
        g_topkw[t * TOPK + k] = wv[k] * inv;
        int e = ids[k];
        int pos = atomicAdd(&g_counts[e], 1);
        g_bucket[e * CAP + pos] = t * TOPK + k;
    }
}

__global__ void k_scan() {
    int s = 0;
    for (int e = 0; e < NEXP; e++) { g_offsets[e] = s; s += g_counts[e]; }
}

/* ======= stage 4: gate/up fp16 HMMA + cp.async 3-stage pipe ===== */
__global__ void __launch_bounds__(256)
k_gemm1() {
    extern __shared__ char smraw[];
    const int e = blockIdx.z;
    const int rows = g_counts[e];
    const int m0 = blockIdx.y * 128;
    if (m0 >= rows) return;
    const int n0 = blockIdx.x * 128;
    const int t = threadIdx.x, w = t >> 5, lane = t & 31;
    const int gid = lane >> 2, tig = lane & 3;
    const int wm = w >> 2, wn = w & 3;

    int* toks = (int*)smraw;
    __half* buf = (__half*)(smraw + 512);
    if (t < 128) {
        int r = m0 + t;
        toks[t] = (r < rows) ? (g_bucket[e * CAP + r] >> 3) : -1;
    }
    __syncthreads();

    const __half* xh  = (const __half*)g_xh;
    const __half* wgh = (const __half*)g_wgh + (size_t)e * HDIM * IDIM;
    const __half* wuh = (const __half*)g_wuh + (size_t)e * HDIM * IDIM;

    const int am = t >> 1, ah = (t & 1) * 8;
    const int tokA = toks[am];
    const uint32_t asz = (tokA >= 0) ? 16u : 0u;
    const __half* aptr = xh + (size_t)(tokA >= 0 ? tokA : 0) * HDIM;
    const int bq = t & 127, bk = bq >> 3, bn = (bq & 7) * 16;
    const __half* bptr = ((t < 128) ? wgh : wuh) + (size_t)bk * IDIM + n0 + bn;
    const int bhoff = A_HALVES + ((t < 128) ? 0 : B_HALVES);

    const uint32_t sb = smem_u32(buf);
    const uint32_t aDst = sb + (uint32_t)(am * A_LDA + ah) * 2;
    const uint32_t bDst = sb + (uint32_t)(bhoff + bk * B_LDB + bn) * 2;

    const int KT = HDIM / 16;
#define G1_ISSUE(s) { \
        const uint32_t so = (uint32_t)((s) % 3) * (G1_STAGE_H * 2); \
        const int kb = (s) * 16; \
        cpa16(aDst + so, aptr + kb + ah, asz); \
        cpa16(bDst + so,      bptr + (size_t)kb * IDIM,     16u); \
        cpa16(bDst + so + 16, bptr + (size_t)kb * IDIM + 8, 16u); \
    }
    G1_ISSUE(0); cpa_commit();
    G1_ISSUE(1); cpa_commit();

    float cg[4][4][4] = {}, cu[4][4][4] = {};
    const int aRow = wm * 64 + (lane & 15);
    const int aK   = (lane >> 4) * 8;
    const int bK   = lane & 15;

    for (int kt = 0; kt < KT; kt++) {
        cpa_wait1();
        __syncthreads();
        if (kt + 2 < KT) G1_ISSUE(kt + 2);
        cpa_commit();
        __half* stc = buf + (kt % 3) * G1_STAGE_H;
        const uint32_t aAddr  = smem_u32(stc + aRow * A_LDA + aK);
        const uint32_t bgAddr = smem_u32(stc + A_HALVES + bK * B_LDB + wn * 32);
        const uint32_t buAddr = bgAddr + B_HALVES * 2;
        uint32_t af[4][4];
#pragma unroll
        for (int mt = 0; mt < 4; mt++) ldsm4(af[mt], aAddr + mt * 16 * A_LDA * 2);
#pragma unroll
        for (int nt = 0; nt < 4; nt++) {
            uint32_t b[2];
            ldsm2t(b, bgAddr + nt * 16);
#pragma unroll
            for (int mt = 0; mt < 4; mt++) mma16(cg[mt][nt], af[mt], b);
            ldsm2t(b, buAddr + nt * 16);
#pragma unroll
            for (int mt = 0; mt < 4; mt++) mma16(cu[mt][nt], af[mt], b);
        }
    }
#undef G1_ISSUE
    /* fused SiLU epilogue -> g_act (fp16) */
    __half* gact = (__half*)g_act4;
    const int off = g_offsets[e];
#pragma unroll
    for (int mt = 0; mt < 4; mt++) {
#pragma unroll
        for (int h = 0; h < 2; h++) {
            const int row = m0 + wm * 64 + mt * 16 + gid + h * 8;
            if (row < rows) {
                __half* dst = gact + (size_t)(off + row) * IDIM + n0 + wn * 32;
#pragma unroll
                for (int nt = 0; nt < 4; nt++) {
                    float g0 = cg[mt][nt][h * 2 + 0], g1 = cg[mt][nt][h * 2 + 1];
                    float u0 = cu[mt][nt][h * 2 + 0], u1 = cu[mt][nt][h * 2 + 1];
                    float o0 = g0 / (1.f + expf(-g0)) * u0;
                    float o1 = g1 / (1.f + expf(-g1)) * u1;
                    *reinterpret_cast<uint32_t*>(dst + nt * 8 + 2 * tig) = pk2(o0, o1);
                }
            }
        }
    }
}

/* ===== stage 5: down-proj fp16 HMMA + fused combine, cp.async 3-stage pipe == */
__global__ void __launch_bounds__(256)
k_gemm2(float* __restrict__ out) {
    extern __shared__ char smraw[];
    const int e = blockIdx.z;
    const int rows = g_counts[e];
    const int m0 = blockIdx.y * 128;
    if (m0 >= rows) return;
    const int n0 = blockIdx.x * 128;
    const int t = threadIdx.x, w = t >> 5, lane = t & 31;
    const int gid = lane >> 2, tig = lane & 3;
    const int wm = w >> 2, wn = w & 3;
    const int off = g_offsets[e];

    int* prs = (int*)smraw;
    __half* buf = (__half*)(smraw + 512);
    if (t < 128) {
        int r = m0 + t;
        prs[t] = (r < rows) ? g_bucket[e * CAP + r] : -1;
    }
    __syncthreads();

    const __half* gact = (const __half*)g_act4;
    const __half* wdh  = (const __half*)g_wdh + (size_t)e * IDIM * HDIM;

    const int am = t >> 1, ah = (t & 1) * 8;
    const uint32_t asz = (m0 + am < rows) ? 16u : 0u;
    const __half* aptr = gact + (size_t)(off + m0 + ((m0 + am < rows) ? am : 0)) * IDIM;
    const int bk = t >> 4, bn = (t & 15) * 8;
    const __half* bptr = wdh + (size_t)bk * HDIM + n0 + bn;

    const uint32_t sb = smem_u32(buf);
    const uint32_t aDst = sb + (uint32_t)(am * A_LDA + ah) * 2;
    const uint32_t bDst = sb + (uint32_t)(A_HALVES + bk * B_LDB + bn) * 2;

    const int KT = IDIM / 16;
#define G2_ISSUE(s) { \
        const uint32_t so = (uint32_t)((s) % 3) * (G2_STAGE_H * 2); \
        const int kb = (s) * 16; \
        cpa16(aDst + so, aptr + kb + ah, asz); \
        cpa16(bDst + so, bptr + (size_t)kb * HDIM, 16u); \
    }
    G2_ISSUE(0); cpa_commit();
    G2_ISSUE(1); cpa_commit();

    float cd[4][4][4] = {};
    const int aRow = wm * 64 + (lane & 15);
    const int aK   = (lane >> 4) * 8;
    const int bK   = lane & 15;

    for (int kt = 0; kt < KT; kt++) {
        cpa_wait1();
        __syncthreads();
        if (kt + 2 < KT) G2_ISSUE(kt + 2);
        cpa_commit();
        __half* stc = buf + (kt % 3) * G2_STAGE_H;
        const uint32_t aAddr = smem_u32(stc + aRow * A_LDA + aK);
        const uint32_t bAddr = smem_u32(stc + A_HALVES + bK * B_LDB + wn * 32);
        uint32_t af[4][4];
#pragma unroll
        for (int mt = 0; mt < 4; mt++) ldsm4(af[mt], aAddr + mt * 16 * A_LDA * 2);
#pragma unroll
        for (int nt = 0; nt < 4; nt++) {
            uint32_t b[2];
            ldsm2t(b, bAddr + nt * 16);
#pragma unroll
            for (int mt = 0; mt < 4; mt++) mma16(cd[mt][nt], af[mt], b);
        }
    }
#undef G2_ISSUE
    /* fused combine: scale by routing weight, atomic accumulate into out */
#pragma unroll
    for (int mt = 0; mt < 4; mt++) {
#pragma unroll
        for (int h = 0; h < 2; h++) {
            const int lr = wm * 64 + mt * 16 + gid + h * 8;
            const int p = prs[lr];
            if (p >= 0) {
                const float wv = g_topkw[p];
                const int tok = p >> 3;
                float* dst = out + (size_t)tok * HDIM + n0 + wn * 32;
#pragma unroll
                for (int nt = 0; nt < 4; nt++) {
                    atomicAdd(dst + nt * 8 + 2 * tig,     wv * cd[mt][nt][h * 2 + 0]);
                    atomicAdd(dst + nt * 8 + 2 * tig + 1, wv * cd[mt][nt][h * 2 + 1]);
                }
            }
        }
    }
}

/* ---------------- launch ---------------- */
extern "C" void kernel_launch(void* const* d_in, const int* /*in_sizes*/, int /*n_in*/,
                              void* d_out, int /*out_size*/) {
    const float* x   = (const float*)d_in[0];
    const float* gw  = (const float*)d_in[1];
    const float* wgt = (const float*)d_in[2];
    const float* wup = (const float*)d_in[3];
    const float* wdn = (const float*)d_in[4];
    float* out = (float*)d_out;

    cudaFuncSetAttribute(k_gemm1, cudaFuncAttributeMaxDynamicSharedMemorySize, G1_SMEM);
    cudaFuncSetAttribute(k_gemm2, cudaFuncAttributeMaxDynamicSharedMemorySize, G2_SMEM);

    const size_t nW = (size_t)NEXP * HDIM * IDIM / 8;   /* uint4 count per weight */
    const size_t nX = (size_t)TTOK * HDIM / 8;

    k_zero_out<<<TTOK * HDIM / 4 / 256, 256>>>((float4*)out);
    k_zero_counts<<<1, 64>>>();
    k_cvt<<<(unsigned)((nW + 255) / 256), 256>>>((const float4*)wgt, 0, nW);
    k_cvt<<<(unsigned)((nW + 255) / 256), 256>>>((const float4*)wup, 1, nW);
    k_cvt<<<(unsigned)((nW + 255) / 256), 256>>>((const float4*)wdn, 2, nW);
    k_cvt<<<(unsigned)((nX + 255) / 256), 256>>>((const float4*)x,   3, nX);
    k_router<<<TTOK / 64, 256>>>(x, gw);
    k_topk<<<TTOK / 256, 256>>>();
    k_scan<<<1, 1>>>();
    k_gemm1<<<dim3(IDIM / 128, CAP / 128, NEXP), 256, G1_SMEM>>>();
    k_gemm2<<<dim3(HDIM / 128, CAP / 128, NEXP), 256, G2_SMEM>>>(out);
}

// round 10
// speedup vs baseline: 1.4529x; 1.0151x over previous
#include <cuda_runtime.h>
#include <cuda_fp16.h>
#include <math.h>
#include <stdint.h>

#define TTOK 4096
#define HDIM 2048
#define NEXP 64
#define TOPK 8
#define IDIM 768
#define NPAIR (TTOK * TOPK)
#define CAP   TTOK

/* ---------------- scratch ---------------- */
__device__ float g_logits[TTOK * NEXP];
__device__ float g_topkw[NPAIR];
__device__ int   g_counts[NEXP];
__device__ int   g_offsets[NEXP];
__device__ int   g_bucket[NEXP * CAP];
__device__ uint4 g_act4[(size_t)NPAIR * IDIM / 8];          /* fp16 activations   */
__device__ uint4 g_xh[(size_t)TTOK * HDIM / 8];             /* fp16 tokens        */
__device__ uint4 g_wgh[(size_t)NEXP * HDIM * IDIM / 8];     /* fp16 w_gate        */
__device__ uint4 g_wuh[(size_t)NEXP * HDIM * IDIM / 8];     /* fp16 w_up          */
__device__ uint4 g_wdh[(size_t)NEXP * IDIM * HDIM / 8];     /* fp16 w_down        */

#define LD4(p) (*reinterpret_cast<const float4*>(p))

/* ---------------- helpers ---------------- */
__device__ __forceinline__ uint32_t smem_u32(const void* p) {
    uint32_t a;
    asm("{ .reg .u64 t; cvta.to.shared.u64 t, %1; cvt.u32.u64 %0, t; }" : "=r"(a) : "l"(p));
    return a;
}
__device__ __forceinline__ uint32_t pk2(float x, float y) {
    __half2 h = __floats2half2_rn(x, y);
    return *reinterpret_cast<uint32_t*>(&h);
}
__device__ __forceinline__ void ldsm4(uint32_t* r, uint32_t addr) {
    asm volatile("ldmatrix.sync.aligned.m8n8.x4.shared.b16 {%0,%1,%2,%3}, [%4];"
                 : "=r"(r[0]), "=r"(r[1]), "=r"(r[2]), "=r"(r[3]) : "r"(addr));
}
__device__ __forceinline__ void ldsm4t(uint32_t* r, uint32_t addr) {
    asm volatile("ldmatrix.sync.aligned.m8n8.x4.trans.shared.b16 {%0,%1,%2,%3}, [%4];"
                 : "=r"(r[0]), "=r"(r[1]), "=r"(r[2]), "=r"(r[3]) : "r"(addr));
}
__device__ __forceinline__ void mma16(float* d, const uint32_t* a, const uint32_t* b) {
    asm volatile(
        "mma.sync.aligned.m16n8k16.row.col.f32.f16.f16.f32 "
        "{%0,%1,%2,%3}, {%4,%5,%6,%7}, {%8,%9}, {%0,%1,%2,%3};"
        : "+f"(d[0]), "+f"(d[1]), "+f"(d[2]), "+f"(d[3])
        : "r"(a[0]), "r"(a[1]), "r"(a[2]), "r"(a[3]), "r"(b[0]), "r"(b[1]));
}
__device__ __forceinline__ void cpa16(uint32_t sdst, const void* gsrc, uint32_t sz) {
    asm volatile("cp.async.cg.shared.global [%0], [%1], 16, %2;"
                 :: "r"(sdst), "l"(gsrc), "r"(sz) : "memory");
}
__device__ __forceinline__ void cpa_commit() {
    asm volatile("cp.async.commit_group;" ::: "memory");
}
__device__ __forceinline__ void cpa_wait1() {
    asm volatile("cp.async.wait_group 1;" ::: "memory");
}

/* smem tiles (halves): A[128][24] (48B rows), B[16][136] (272B rows) */
#define A_LDA 24
#define B_LDB 136
#define A_HALVES (128 * A_LDA)
#define B_HALVES (16 * B_LDB)
#define G1_STAGE_H (A_HALVES + 2 * B_HALVES)
#define G1_SMEM (512 + 3 * G1_STAGE_H * 2)
#define G2_STAGE_H (A_HALVES + B_HALVES)
#define G2_SMEM (512 + 3 * G2_STAGE_H * 2)

/* ---------------- small kernels ---------------- */
__global__ void k_zero_counts() { if (threadIdx.x < NEXP) g_counts[threadIdx.x] = 0; }

__global__ void k_zero_out(float4* __restrict__ out) {
    size_t i = (size_t)blockIdx.x * blockDim.x + threadIdx.x;
    if (i < (size_t)TTOK * HDIM / 4) out[i] = make_float4(0.f, 0.f, 0.f, 0.f);
}

/* fp32 -> fp16 bulk convert. dst selected DEVICE-SIDE (host shadow-symbol trap). */
__global__ void __launch_bounds__(256) k_cvt(const float4* __restrict__ src,
                                             int which, size_t n8) {
    size_t i = (size_t)blockIdx.x * blockDim.x + threadIdx.x;
    if (i >= n8) return;
    uint4* dst = (which == 0) ? g_wgh : (which == 1) ? g_wuh : (which == 2) ? g_wdh : g_xh;
    float4 a = src[2 * i], b = src[2 * i + 1];
    dst[i] = make_uint4(pk2(a.x, a.y), pk2(a.z, a.w), pk2(b.x, b.y), pk2(b.z, b.w));
}

__global__ void __launch_bounds__(256) k_router(const float* __restrict__ x,
                                                const float* __restrict__ gw) {
    __shared__ float As[16][64];
    __shared__ float Bs[16][64];
    const int t = threadIdx.x;
    const int m0 = blockIdx.x * 64;
    const int tx = t & 15, ty = t >> 4;
    const int mload = t >> 2;
    const int kq = (t & 3) * 4;
    float acc[4][4] = {};
    for (int k0 = 0; k0 < HDIM; k0 += 16) {
        float4 av = LD4(x + (size_t)(m0 + mload) * HDIM + k0 + kq);
        float4 bv = LD4(gw + (size_t)mload * HDIM + k0 + kq);
        __syncthreads();
        As[kq + 0][mload] = av.x; As[kq + 1][mload] = av.y;
        As[kq + 2][mload] = av.z; As[kq + 3][mload] = av.w;
        Bs[kq + 0][mload] = bv.x; Bs[kq + 1][mload] = bv.y;
        Bs[kq + 2][mload] = bv.z; Bs[kq + 3][mload] = bv.w;
        __syncthreads();
#pragma unroll
        for (int k = 0; k < 16; k++) {
            float4 a = LD4(&As[k][ty * 4]);
            float4 b = LD4(&Bs[k][tx * 4]);
            float ax[4] = {a.x, a.y, a.z, a.w};
            float bx[4] = {b.x, b.y, b.z, b.w};
#pragma unroll
            for (int i = 0; i < 4; i++)
#pragma unroll
                for (int j = 0; j < 4; j++)
                    acc[i][j] = fmaf(ax[i], bx[j], acc[i][j]);
        }
    }
#pragma unroll
    for (int i = 0; i < 4; i++)
#pragma unroll
        for (int j = 0; j < 4; j++)
            g_logits[(size_t)(m0 + ty * 4 + i) * NEXP + tx * 4 + j] = acc[i][j];
}

__global__ void k_topk() {
    int t = blockIdx.x * blockDim.x + threadIdx.x;
    if (t >= TTOK) return;
    float l[NEXP];
    for (int e = 0; e < NEXP; e++) l[e] = g_logits[(size_t)t * NEXP + e];
    float vals[TOPK]; int ids[TOPK];
    for (int k = 0; k < TOPK; k++) {
        float best = -3.4e38f; int bi = 0;
        for (int e = 0; e < NEXP; e++)
            if (l[e] > best) { best = l[e]; bi = e; }
        vals[k] = best; ids[k] = bi; l[bi] = -3.4e38f;
    }
    float m = vals[0], s = 0.f, wv[TOPK];
    for (int k = 0; k < TOPK; k++) { wv[k] = expf(vals[k] - m); s += wv[k]; }
    float inv = 1.f / s;
    for (int k = 0; k < TOPK; k++) {
        g_topkw[t * TOPK + k] = wv[k] * inv;
        int e = ids[k];
        int pos = atomicAdd(&g_counts[e], 1);
        g_bucket[e * CAP + pos] = t * TOPK + k;
    }
}

__global__ void k_scan() {
    int s = 0;
    for (int e = 0; e < NEXP; e++) { g_offsets[e] = s; s += g_counts[e]; }
}

/* ======= stage 4: gate/up fp16 HMMA + cp.async 3-stage pipe ===== */
__global__ void __launch_bounds__(256)
k_gemm1() {
    extern __shared__ char smraw[];
    const int e = blockIdx.z;
    const int rows = g_counts[e];
    const int m0 = blockIdx.y * 128;
    if (m0 >= rows) return;
    const int n0 = blockIdx.x * 128;
    const int t = threadIdx.x, w = t >> 5, lane = t & 31;
    const int gid = lane >> 2, tig = lane & 3;
    const int wm = w >> 2, wn = w & 3;

    int* toks = (int*)smraw;
    __half* buf = (__half*)(smraw + 512);
    if (t < 128) {
        int r = m0 + t;
        toks[t] = (r < rows) ? (g_bucket[e * CAP + r] >> 3) : -1;
    }
    __syncthreads();

    const __half* xh  = (const __half*)g_xh;
    const __half* wgh = (const __half*)g_wgh + (size_t)e * HDIM * IDIM;
    const __half* wuh = (const __half*)g_wuh + (size_t)e * HDIM * IDIM;

    const int am = t >> 1, ah = (t & 1) * 8;
    const int tokA = toks[am];
    const uint32_t asz = (tokA >= 0) ? 16u : 0u;
    const __half* aptr = xh + (size_t)(tokA >= 0 ? tokA : 0) * HDIM;
    const int bq = t & 127, bk = bq >> 3, bn = (bq & 7) * 16;
    const __half* bptr = ((t < 128) ? wgh : wuh) + (size_t)bk * IDIM + n0 + bn;
    const int bhoff = A_HALVES + ((t < 128) ? 0 : B_HALVES);

    const uint32_t sb = smem_u32(buf);
    const uint32_t aDst = sb + (uint32_t)(am * A_LDA + ah) * 2;
    const uint32_t bDst = sb + (uint32_t)(bhoff + bk * B_LDB + bn) * 2;

    const int KT = HDIM / 16;
#define G1_ISSUE(s) { \
        const uint32_t so = (uint32_t)((s) % 3) * (G1_STAGE_H * 2); \
        const int kb = (s) * 16; \
        cpa16(aDst + so, aptr + kb + ah, asz); \
        cpa16(bDst + so,      bptr + (size_t)kb * IDIM,     16u); \
        cpa16(bDst + so + 16, bptr + (size_t)kb * IDIM + 8, 16u); \
    }
    G1_ISSUE(0); cpa_commit();
    G1_ISSUE(1); cpa_commit();

    float cg[4][4][4] = {}, cu[4][4][4] = {};
    const int aRow = wm * 64 + (lane & 15);
    const int aK   = (lane >> 4) * 8;
    /* B x4-trans per-lane: lanes 0-15 -> k rows of n-oct0, lanes 16-31 -> n-oct1 */
    const int bRow = lane & 15;
    const int bOct = (lane >> 4) * 8;

    for (int kt = 0; kt < KT; kt++) {
        cpa_wait1();
        __syncthreads();
        if (kt + 2 < KT) G1_ISSUE(kt + 2);
        cpa_commit();
        __half* stc = buf + (kt % 3) * G1_STAGE_H;
        const uint32_t aAddr  = smem_u32(stc + aRow * A_LDA + aK);
        const uint32_t bgAddr = smem_u32(stc + A_HALVES + bRow * B_LDB + wn * 32 + bOct);
        const uint32_t buAddr = bgAddr + B_HALVES * 2;
        /* batch-load ALL fragments, then back-to-back MMAs */
        uint32_t af[4][4], bg[2][4], bu[2][4];
#pragma unroll
        for (int mt = 0; mt < 4; mt++) ldsm4(af[mt], aAddr + mt * 16 * A_LDA * 2);
#pragma unroll
        for (int p = 0; p < 2; p++) {
            ldsm4t(bg[p], bgAddr + p * 32);
            ldsm4t(bu[p], buAddr + p * 32);
        }
#pragma unroll
        for (int nt = 0; nt < 4; nt++) {
            const uint32_t* b = &bg[nt >> 1][(nt & 1) * 2];
#pragma unroll
            for (int mt = 0; mt < 4; mt++) mma16(cg[mt][nt], af[mt], b);
        }
#pragma unroll
        for (int nt = 0; nt < 4; nt++) {
            const uint32_t* b = &bu[nt >> 1][(nt & 1) * 2];
#pragma unroll
            for (int mt = 0; mt < 4; mt++) mma16(cu[mt][nt], af[mt], b);
        }
    }
#undef G1_ISSUE
    /* fused SiLU epilogue -> g_act (fp16) */
    __half* gact = (__half*)g_act4;
    const int off = g_offsets[e];
#pragma unroll
    for (int mt = 0; mt < 4; mt++) {
#pragma unroll
        for (int h = 0; h < 2; h++) {
            const int row = m0 + wm * 64 + mt * 16 + gid + h * 8;
            if (row < rows) {
                __half* dst = gact + (size_t)(off + row) * IDIM + n0 + wn * 32;
#pragma unroll
                for (int nt = 0; nt < 4; nt++) {
                    float g0 = cg[mt][nt][h * 2 + 0], g1 = cg[mt][nt][h * 2 + 1];
                    float u0 = cu[mt][nt][h * 2 + 0], u1 = cu[mt][nt][h * 2 + 1];
                    float o0 = g0 / (1.f + expf(-g0)) * u0;
                    float o1 = g1 / (1.f + expf(-g1)) * u1;
                    *reinterpret_cast<uint32_t*>(dst + nt * 8 + 2 * tig) = pk2(o0, o1);
                }
            }
        }
    }
}

/* ===== stage 5: down-proj fp16 HMMA + fused combine, cp.async 3-stage pipe == */
__global__ void __launch_bounds__(256)
k_gemm2(float* __restrict__ out) {
    extern __shared__ char smraw[];
    const int e = blockIdx.z;
    const int rows = g_counts[e];
    const int m0 = blockIdx.y * 128;
    if (m0 >= rows) return;
    const int n0 = blockIdx.x * 128;
    const int t = threadIdx.x, w = t >> 5, lane = t & 31;
    const int gid = lane >> 2, tig = lane & 3;
    const int wm = w >> 2, wn = w & 3;
    const int off = g_offsets[e];

    int* prs = (int*)smraw;
    __half* buf = (__half*)(smraw + 512);
    if (t < 128) {
        int r = m0 + t;
        prs[t] = (r < rows) ? g_bucket[e * CAP + r] : -1;
    }
    __syncthreads();

    const __half* gact = (const __half*)g_act4;
    const __half* wdh  = (const __half*)g_wdh + (size_t)e * IDIM * HDIM;

    const int am = t >> 1, ah = (t & 1) * 8;
    const uint32_t asz = (m0 + am < rows) ? 16u : 0u;
    const __half* aptr = gact + (size_t)(off + m0 + ((m0 + am < rows) ? am : 0)) * IDIM;
    const int bk = t >> 4, bn = (t & 15) * 8;
    const __half* bptr = wdh + (size_t)bk * HDIM + n0 + bn;

    const uint32_t sb = smem_u32(buf);
    const uint32_t aDst = sb + (uint32_t)(am * A_LDA + ah) * 2;
    const uint32_t bDst = sb + (uint32_t)(A_HALVES + bk * B_LDB + bn) * 2;

    const int KT = IDIM / 16;
#define G2_ISSUE(s) { \
        const uint32_t so = (uint32_t)((s) % 3) * (G2_STAGE_H * 2); \
        const int kb = (s) * 16; \
        cpa16(aDst + so, aptr + kb + ah, asz); \
        cpa16(bDst + so, bptr + (size_t)kb * HDIM, 16u); \
    }
    G2_ISSUE(0); cpa_commit();
    G2_ISSUE(1); cpa_commit();

    float cd[4][4][4] = {};
    const int aRow = wm * 64 + (lane & 15);
    const int aK   = (lane >> 4) * 8;
    const int bRow = lane & 15;
    const int bOct = (lane >> 4) * 8;

    for (int kt = 0; kt < KT; kt++) {
        cpa_wait1();
        __syncthreads();
        if (kt + 2 < KT) G2_ISSUE(kt + 2);
        cpa_commit();
        __half* stc = buf + (kt % 3) * G2_STAGE_H;
        const uint32_t aAddr = smem_u32(stc + aRow * A_LDA + aK);
        const uint32_t bAddr = smem_u32(stc + A_HALVES + bRow * B_LDB + wn * 32 + bOct);
        uint32_t af[4][4], bd[2][4];
#pragma unroll
        for (int mt = 0; mt < 4; mt++) ldsm4(af[mt], aAddr + mt * 16 * A_LDA * 2);
#pragma unroll
        for (int p = 0; p < 2; p++) ldsm4t(bd[p], bAddr + p * 32);
#pragma unroll
        for (int nt = 0; nt < 4; nt++) {
            const uint32_t* b = &bd[nt >> 1][(nt & 1) * 2];
#pragma unroll
            for (int mt = 0; mt < 4; mt++) mma16(cd[mt][nt], af[mt], b);
        }
    }
#undef G2_ISSUE
    /* fused combine: scale by routing weight, atomic accumulate into out */
#pragma unroll
    for (int mt = 0; mt < 4; mt++) {
#pragma unroll
        for (int h = 0; h < 2; h++) {
            const int lr = wm * 64 + mt * 16 + gid + h * 8;
            const int p = prs[lr];
            if (p >= 0) {
                const float wv = g_topkw[p];
                const int tok = p >> 3;
                float* dst = out + (size_t)tok * HDIM + n0 + wn * 32;
#pragma unroll
                for (int nt = 0; nt < 4; nt++) {
                    atomicAdd(dst + nt * 8 + 2 * tig,     wv * cd[mt][nt][h * 2 + 0]);
                    atomicAdd(dst + nt * 8 + 2 * tig + 1, wv * cd[mt][nt][h * 2 + 1]);
                }
            }
        }
    }
}

/* ---------------- launch ---------------- */
extern "C" void kernel_launch(void* const* d_in, const int* /*in_sizes*/, int /*n_in*/,
                              void* d_out, int /*out_size*/) {
    const float* x   = (const float*)d_in[0];
    const float* gw  = (const float*)d_in[1];
    const float* wgt = (const float*)d_in[2];
    const float* wup = (const float*)d_in[3];
    const float* wdn = (const float*)d_in[4];
    float* out = (float*)d_out;

    cudaFuncSetAttribute(k_gemm1, cudaFuncAttributeMaxDynamicSharedMemorySize, G1_SMEM);
    cudaFuncSetAttribute(k_gemm2, cudaFuncAttributeMaxDynamicSharedMemorySize, G2_SMEM);

    const size_t nW = (size_t)NEXP * HDIM * IDIM / 8;
    const size_t nX = (size_t)TTOK * HDIM / 8;

    k_zero_out<<<TTOK * HDIM / 4 / 256, 256>>>((float4*)out);
    k_zero_counts<<<1, 64>>>();
    k_cvt<<<(unsigned)((nW + 255) / 256), 256>>>((const float4*)wgt, 0, nW);
    k_cvt<<<(unsigned)((nW + 255) / 256), 256>>>((const float4*)wup, 1, nW);
    k_cvt<<<(unsigned)((nW + 255) / 256), 256>>>((const float4*)wdn, 2, nW);
    k_cvt<<<(unsigned)((nX + 255) / 256), 256>>>((const float4*)x,   3, nX);
    k_router<<<TTOK / 64, 256>>>(x, gw);
    k_topk<<<TTOK / 256, 256>>>();
    k_scan<<<1, 1>>>();
    k_gemm1<<<dim3(IDIM / 128, CAP / 128, NEXP), 256, G1_SMEM>>>();
    k_gemm2<<<dim3(HDIM / 128, CAP / 128, NEXP), 256, G2_SMEM>>>(out);
}

// round 11
// speedup vs baseline: 1.7169x; 1.1817x over previous
#include <cuda_runtime.h>
#include <cuda_fp16.h>
#include <math.h>
#include <stdint.h>

#define TTOK 4096
#define HDIM 2048
#define NEXP 64
#define TOPK 8
#define IDIM 768
#define NPAIR (TTOK * TOPK)
#define CAP   TTOK

/* ---------------- scratch ---------------- */
__device__ float g_logits[TTOK * NEXP];
__device__ float g_topkw[NPAIR];
__device__ int   g_counts[NEXP];
__device__ int   g_offsets[NEXP];
__device__ int   g_bucket[NEXP * CAP];
__device__ uint4 g_act4[(size_t)NPAIR * IDIM / 8];          /* fp16 silu(g)*u     */
__device__ uint4 g_gb[(size_t)NPAIR * IDIM / 8];            /* fp16 gate result   */
__device__ uint4 g_ub[(size_t)NPAIR * IDIM / 8];            /* fp16 up result     */
__device__ uint4 g_xh[(size_t)TTOK * HDIM / 8];             /* fp16 tokens        */
__device__ uint4 g_wgh[(size_t)NEXP * HDIM * IDIM / 8];     /* fp16 w_gate        */
__device__ uint4 g_wuh[(size_t)NEXP * HDIM * IDIM / 8];     /* fp16 w_up          */
__device__ uint4 g_wdh[(size_t)NEXP * IDIM * HDIM / 8];     /* fp16 w_down        */

#define LD4(p) (*reinterpret_cast<const float4*>(p))

/* ---------------- helpers ---------------- */
__device__ __forceinline__ uint32_t smem_u32(const void* p) {
    uint32_t a;
    asm("{ .reg .u64 t; cvta.to.shared.u64 t, %1; cvt.u32.u64 %0, t; }" : "=r"(a) : "l"(p));
    return a;
}
__device__ __forceinline__ uint32_t pk2(float x, float y) {
    __half2 h = __floats2half2_rn(x, y);
    return *reinterpret_cast<uint32_t*>(&h);
}
__device__ __forceinline__ void ldsm4(uint32_t* r, uint32_t addr) {
    asm volatile("ldmatrix.sync.aligned.m8n8.x4.shared.b16 {%0,%1,%2,%3}, [%4];"
                 : "=r"(r[0]), "=r"(r[1]), "=r"(r[2]), "=r"(r[3]) : "r"(addr));
}
__device__ __forceinline__ void ldsm4t(uint32_t* r, uint32_t addr) {
    asm volatile("ldmatrix.sync.aligned.m8n8.x4.trans.shared.b16 {%0,%1,%2,%3}, [%4];"
                 : "=r"(r[0]), "=r"(r[1]), "=r"(r[2]), "=r"(r[3]) : "r"(addr));
}
__device__ __forceinline__ void mma16(float* d, const uint32_t* a, const uint32_t* b) {
    asm volatile(
        "mma.sync.aligned.m16n8k16.row.col.f32.f16.f16.f32 "
        "{%0,%1,%2,%3}, {%4,%5,%6,%7}, {%8,%9}, {%0,%1,%2,%3};"
        : "+f"(d[0]), "+f"(d[1]), "+f"(d[2]), "+f"(d[3])
        : "r"(a[0]), "r"(a[1]), "r"(a[2]), "r"(a[3]), "r"(b[0]), "r"(b[1]));
}
__device__ __forceinline__ void cpa16(uint32_t sdst, const void* gsrc, uint32_t sz) {
    asm volatile("cp.async.cg.shared.global [%0], [%1], 16, %2;"
                 :: "r"(sdst), "l"(gsrc), "r"(sz) : "memory");
}
__device__ __forceinline__ void cpa_commit() {
    asm volatile("cp.async.commit_group;" ::: "memory");
}
__device__ __forceinline__ void cpa_wait1() {
    asm volatile("cp.async.wait_group 1;" ::: "memory");
}

/* smem tiles (halves): A[128][24] (48B rows), B[16][136] (272B rows) */
#define A_LDA 24
#define B_LDB 136
#define A_HALVES (128 * A_LDA)
#define B_HALVES (16 * B_LDB)
#define G_STAGE_H (A_HALVES + B_HALVES)          /* 5248 */
#define G_SMEM (512 + 3 * G_STAGE_H * 2)         /* ~32KB -> 2 CTAs/SM */

/* ---------------- small kernels ---------------- */
__global__ void k_zero_counts() { if (threadIdx.x < NEXP) g_counts[threadIdx.x] = 0; }

__global__ void k_zero_out(float4* __restrict__ out) {
    size_t i = (size_t)blockIdx.x * blockDim.x + threadIdx.x;
    if (i < (size_t)TTOK * HDIM / 4) out[i] = make_float4(0.f, 0.f, 0.f, 0.f);
}

/* fp32 -> fp16 bulk convert. dst selected DEVICE-SIDE (host shadow-symbol trap). */
__global__ void __launch_bounds__(256) k_cvt(const float4* __restrict__ src,
                                             int which, size_t n8) {
    size_t i = (size_t)blockIdx.x * blockDim.x + threadIdx.x;
    if (i >= n8) return;
    uint4* dst = (which == 0) ? g_wgh : (which == 1) ? g_wuh : (which == 2) ? g_wdh : g_xh;
    float4 a = src[2 * i], b = src[2 * i + 1];
    dst[i] = make_uint4(pk2(a.x, a.y), pk2(a.z, a.w), pk2(b.x, b.y), pk2(b.z, b.w));
}

/* elementwise act = silu(g) * u, fp16 in/out, 8 elems/thread */
__global__ void __launch_bounds__(256) k_silu() {
    size_t i = (size_t)blockIdx.x * blockDim.x + threadIdx.x;
    if (i >= (size_t)NPAIR * IDIM / 8) return;
    uint4 gv = g_gb[i], uv = g_ub[i];
    const uint32_t* gw = &gv.x;
    const uint32_t* uw = &uv.x;
    uint4 o;
    uint32_t* ow = &o.x;
#pragma unroll
    for (int j = 0; j < 4; j++) {
        __half2 gh = *reinterpret_cast<const __half2*>(&gw[j]);
        __half2 uh = *reinterpret_cast<const __half2*>(&uw[j]);
        float2 gf = __half22float2(gh), uf = __half22float2(uh);
        float o0 = gf.x / (1.f + expf(-gf.x)) * uf.x;
        float o1 = gf.y / (1.f + expf(-gf.y)) * uf.y;
        ow[j] = pk2(o0, o1);
    }
    g_act4[i] = o;
}

__global__ void __launch_bounds__(256) k_router(const float* __restrict__ x,
                                                const float* __restrict__ gw) {
    __shared__ float As[16][64];
    __shared__ float Bs[16][64];
    const int t = threadIdx.x;
    const int m0 = blockIdx.x * 64;
    const int tx = t & 15, ty = t >> 4;
    const int mload = t >> 2;
    const int kq = (t & 3) * 4;
    float acc[4][4] = {};
    for (int k0 = 0; k0 < HDIM; k0 += 16) {
        float4 av = LD4(x + (size_t)(m0 + mload) * HDIM + k0 + kq);
        float4 bv = LD4(gw + (size_t)mload * HDIM + k0 + kq);
        __syncthreads();
        As[kq + 0][mload] = av.x; As[kq + 1][mload] = av.y;
        As[kq + 2][mload] = av.z; As[kq + 3][mload] = av.w;
        Bs[kq + 0][mload] = bv.x; Bs[kq + 1][mload] = bv.y;
        Bs[kq + 2][mload] = bv.z; Bs[kq + 3][mload] = bv.w;
        __syncthreads();
#pragma unroll
        for (int k = 0; k < 16; k++) {
            float4 a = LD4(&As[k][ty * 4]);
            float4 b = LD4(&Bs[k][tx * 4]);
            float ax[4] = {a.x, a.y, a.z, a.w};
            float bx[4] = {b.x, b.y, b.z, b.w};
#pragma unroll
            for (int i = 0; i < 4; i++)
#pragma unroll
                for (int j = 0; j < 4; j++)
                    acc[i][j] = fmaf(ax[i], bx[j], acc[i][j]);
        }
    }
#pragma unroll
    for (int i = 0; i < 4; i++)
#pragma unroll
        for (int j = 0; j < 4; j++)
            g_logits[(size_t)(m0 + ty * 4 + i) * NEXP + tx * 4 + j] = acc[i][j];
}

__global__ void k_topk() {
    int t = blockIdx.x * blockDim.x + threadIdx.x;
    if (t >= TTOK) return;
    float l[NEXP];
    for (int e = 0; e < NEXP; e++) l[e] = g_logits[(size_t)t * NEXP + e];
    float vals[TOPK]; int ids[TOPK];
    for (int k = 0; k < TOPK; k++) {
        float best = -3.4e38f; int bi = 0;
        for (int e = 0; e < NEXP; e++)
            if (l[e] > best) { best = l[e]; bi = e; }
        vals[k] = best; ids[k] = bi; l[bi] = -3.4e38f;
    }
    float m = vals[0], s = 0.f, wv[TOPK];
    for (int k = 0; k < TOPK; k++) { wv[k] = expf(vals[k] - m); s += wv[k]; }
    float inv = 1.f / s;
    for (int k = 0; k < TOPK; k++) {
        g_topkw[t * TOPK + k] = wv[k] * inv;
        int e = ids[k];
        int pos = atomicAdd(&g_counts[e], 1);
        g_bucket[e * CAP + pos] = t * TOPK + k;
    }
}

__global__ void k_scan() {
    int s = 0;
    for (int e = 0; e < NEXP; e++) { g_offsets[e] = s; s += g_counts[e]; }
}

/* ======= stage 4: gate OR up fp16 HMMA (split for 2 CTAs/SM) ===== */
__global__ void __launch_bounds__(256, 2)
k_gemm1() {
    extern __shared__ char smraw[];
    const int e = blockIdx.z >> 1;
    const int which = blockIdx.z & 1;
    const int rows = g_counts[e];
    const int m0 = blockIdx.y * 128;
    if (m0 >= rows) return;
    const int n0 = blockIdx.x * 128;
    const int t = threadIdx.x, w = t >> 5, lane = t & 31;
    const int gid = lane >> 2, tig = lane & 3;
    const int wm = w >> 2, wn = w & 3;

    int* toks = (int*)smraw;
    __half* buf = (__half*)(smraw + 512);
    if (t < 128) {
        int r = m0 + t;
        toks[t] = (r < rows) ? (g_bucket[e * CAP + r] >> 3) : -1;
    }
    __syncthreads();

    const __half* xh = (const __half*)g_xh;
    const __half* wh = (const __half*)(which ? g_wuh : g_wgh) + (size_t)e * HDIM * IDIM;

    const int am = t >> 1, ah = (t & 1) * 8;
    const int tokA = toks[am];
    const uint32_t asz = (tokA >= 0) ? 16u : 0u;
    const __half* aptr = xh + (size_t)(tokA >= 0 ? tokA : 0) * HDIM;
    const int bk = t >> 4, bn = (t & 15) * 8;
    const __half* bptr = wh + (size_t)bk * IDIM + n0 + bn;

    const uint32_t sb = smem_u32(buf);
    const uint32_t aDst = sb + (uint32_t)(am * A_LDA + ah) * 2;
    const uint32_t bDst = sb + (uint32_t)(A_HALVES + bk * B_LDB + bn) * 2;

    const int KT = HDIM / 16;
#define G1_ISSUE(s) { \
        const uint32_t so = (uint32_t)((s) % 3) * (G_STAGE_H * 2); \
        const int kb = (s) * 16; \
        cpa16(aDst + so, aptr + kb + ah, asz); \
        cpa16(bDst + so, bptr + (size_t)kb * IDIM, 16u); \
    }
    G1_ISSUE(0); cpa_commit();
    G1_ISSUE(1); cpa_commit();

    float cg[4][4][4] = {};
    const int aRow = wm * 64 + (lane & 15);
    const int aK   = (lane >> 4) * 8;
    const int bRow = lane & 15;
    const int bOct = (lane >> 4) * 8;

    for (int kt = 0; kt < KT; kt++) {
        cpa_wait1();
        __syncthreads();
        if (kt + 2 < KT) G1_ISSUE(kt + 2);
        cpa_commit();
        __half* stc = buf + (kt % 3) * G_STAGE_H;
        const uint32_t aAddr = smem_u32(stc + aRow * A_LDA + aK);
        const uint32_t bAddr = smem_u32(stc + A_HALVES + bRow * B_LDB + wn * 32 + bOct);
        uint32_t af[4][4], bg[2][4];
#pragma unroll
        for (int mt = 0; mt < 4; mt++) ldsm4(af[mt], aAddr + mt * 16 * A_LDA * 2);
#pragma unroll
        for (int p = 0; p < 2; p++) ldsm4t(bg[p], bAddr + p * 32);
#pragma unroll
        for (int nt = 0; nt < 4; nt++) {
            const uint32_t* b = &bg[nt >> 1][(nt & 1) * 2];
#pragma unroll
            for (int mt = 0; mt < 4; mt++) mma16(cg[mt][nt], af[mt], b);
        }
    }
#undef G1_ISSUE
    /* epilogue -> raw fp16 gate/up buffer */
    __half* gout = (__half*)(which ? g_ub : g_gb);
    const int off = g_offsets[e];
#pragma unroll
    for (int mt = 0; mt < 4; mt++) {
#pragma unroll
        for (int h = 0; h < 2; h++) {
            const int row = m0 + wm * 64 + mt * 16 + gid + h * 8;
            if (row < rows) {
                __half* dst = gout + (size_t)(off + row) * IDIM + n0 + wn * 32;
#pragma unroll
                for (int nt = 0; nt < 4; nt++)
                    *reinterpret_cast<uint32_t*>(dst + nt * 8 + 2 * tig) =
                        pk2(cg[mt][nt][h * 2 + 0], cg[mt][nt][h * 2 + 1]);
            }
        }
    }
}

/* ===== stage 5: down-proj fp16 HMMA + fused combine ===== */
__global__ void __launch_bounds__(256, 2)
k_gemm2(float* __restrict__ out) {
    extern __shared__ char smraw[];
    const int e = blockIdx.z;
    const int rows = g_counts[e];
    const int m0 = blockIdx.y * 128;
    if (m0 >= rows) return;
    const int n0 = blockIdx.x * 128;
    const int t = threadIdx.x, w = t >> 5, lane = t & 31;
    const int gid = lane >> 2, tig = lane & 3;
    const int wm = w >> 2, wn = w & 3;
    const int off = g_offsets[e];

    int* prs = (int*)smraw;
    __half* buf = (__half*)(smraw + 512);
    if (t < 128) {
        int r = m0 + t;
        prs[t] = (r < rows) ? g_bucket[e * CAP + r] : -1;
    }
    __syncthreads();

    const __half* gact = (const __half*)g_act4;
    const __half* wdh  = (const __half*)g_wdh + (size_t)e * IDIM * HDIM;

    const int am = t >> 1, ah = (t & 1) * 8;
    const uint32_t asz = (m0 + am < rows) ? 16u : 0u;
    const __half* aptr = gact + (size_t)(off + m0 + ((m0 + am < rows) ? am : 0)) * IDIM;
    const int bk = t >> 4, bn = (t & 15) * 8;
    const __half* bptr = wdh + (size_t)bk * HDIM + n0 + bn;

    const uint32_t sb = smem_u32(buf);
    const uint32_t aDst = sb + (uint32_t)(am * A_LDA + ah) * 2;
    const uint32_t bDst = sb + (uint32_t)(A_HALVES + bk * B_LDB + bn) * 2;

    const int KT = IDIM / 16;
#define G2_ISSUE(s) { \
        const uint32_t so = (uint32_t)((s) % 3) * (G_STAGE_H * 2); \
        const int kb = (s) * 16; \
        cpa16(aDst + so, aptr + kb + ah, asz); \
        cpa16(bDst + so, bptr + (size_t)kb * HDIM, 16u); \
    }
    G2_ISSUE(0); cpa_commit();
    G2_ISSUE(1); cpa_commit();

    float cd[4][4][4] = {};
    const int aRow = wm * 64 + (lane & 15);
    const int aK   = (lane >> 4) * 8;
    const int bRow = lane & 15;
    const int bOct = (lane >> 4) * 8;

    for (int kt = 0; kt < KT; kt++) {
        cpa_wait1();
        __syncthreads();
        if (kt + 2 < KT) G2_ISSUE(kt + 2);
        cpa_commit();
        __half* stc = buf + (kt % 3) * G_STAGE_H;
        const uint32_t aAddr = smem_u32(stc + aRow * A_LDA + aK);
        const uint32_t bAddr = smem_u32(stc + A_HALVES + bRow * B_LDB + wn * 32 + bOct);
        uint32_t af[4][4], bd[2][4];
#pragma unroll
        for (int mt = 0; mt < 4; mt++) ldsm4(af[mt], aAddr + mt * 16 * A_LDA * 2);
#pragma unroll
        for (int p = 0; p < 2; p++) ldsm4t(bd[p], bAddr + p * 32);
#pragma unroll
        for (int nt = 0; nt < 4; nt++) {
            const uint32_t* b = &bd[nt >> 1][(nt & 1) * 2];
#pragma unroll
            for (int mt = 0; mt < 4; mt++) mma16(cd[mt][nt], af[mt], b);
        }
    }
#undef G2_ISSUE
    /* fused combine: scale by routing weight, atomic accumulate into out */
#pragma unroll
    for (int mt = 0; mt < 4; mt++) {
#pragma unroll
        for (int h = 0; h < 2; h++) {
            const int lr = wm * 64 + mt * 16 + gid + h * 8;
            const int p = prs[lr];
            if (p >= 0) {
                const float wv = g_topkw[p];
                const int tok = p >> 3;
                float* dst = out + (size_t)tok * HDIM + n0 + wn * 32;
#pragma unroll
                for (int nt = 0; nt < 4; nt++) {
                    atomicAdd(dst + nt * 8 + 2 * tig,     wv * cd[mt][nt][h * 2 + 0]);
                    atomicAdd(dst + nt * 8 + 2 * tig + 1, wv * cd[mt][nt][h * 2 + 1]);
                }
            }
        }
    }
}

/* ---------------- launch ---------------- */
extern "C" void kernel_launch(void* const* d_in, const int* /*in_sizes*/, int /*n_in*/,
                              void* d_out, int /*out_size*/) {
    const float* x   = (const float*)d_in[0];
    const float* gw  = (const float*)d_in[1];
    const float* wgt = (const float*)d_in[2];
    const float* wup = (const float*)d_in[3];
    const float* wdn = (const float*)d_in[4];
    float* out = (float*)d_out;

    cudaFuncSetAttribute(k_gemm1, cudaFuncAttributeMaxDynamicSharedMemorySize, G_SMEM);
    cudaFuncSetAttribute(k_gemm2, cudaFuncAttributeMaxDynamicSharedMemorySize, G_SMEM);

    const size_t nW = (size_t)NEXP * HDIM * IDIM / 8;
    const size_t nX = (size_t)TTOK * HDIM / 8;
    const size_t nA = (size_t)NPAIR * IDIM / 8;

    k_zero_out<<<TTOK * HDIM / 4 / 256, 256>>>((float4*)out);
    k_zero_counts<<<1, 64>>>();
    k_cvt<<<(unsigned)((nW + 255) / 256), 256>>>((const float4*)wgt, 0, nW);
    k_cvt<<<(unsigned)((nW + 255) / 256), 256>>>((const float4*)wup, 1, nW);
    k_cvt<<<(unsigned)((nW + 255) / 256), 256>>>((const float4*)wdn, 2, nW);
    k_cvt<<<(unsigned)((nX + 255) / 256), 256>>>((const float4*)x,   3, nX);
    k_router<<<TTOK / 64, 256>>>(x, gw);
    k_topk<<<TTOK / 256, 256>>>();
    k_scan<<<1, 1>>>();
    k_gemm1<<<dim3(IDIM / 128, CAP / 128, NEXP * 2), 256, G_SMEM>>>();
    k_silu<<<(unsigned)((nA + 255) / 256), 256>>>();
    k_gemm2<<<dim3(HDIM / 128, CAP / 128, NEXP), 256, G_SMEM>>>(out);
}